// round 17
// baseline (speedup 1.0000x reference)
#include <cuda_runtime.h>
#include <cuda_fp16.h>
#include <cstddef>

// ---------------------------------------------------------------------------
// StackSAModuleMSG — both GEMMs fp16 m16n8k16 (fp32 accum). gemm2 uses a
// paired-word smem layout: word w of each 8-word k16 group at slot
// 2*(w&3)+(w>>2), so each mma fragment pair is ONE LDS.64; pitch 72
// (==8 mod 32) makes those LDS.64 conflict-free.
// X1 never touches DRAM (fused raw max/min pooling in gemm2 registers).
// B=4, NB=8192, MB=2048, M=8192, C_IN=64, CIN=67.
// Scale 0: r=0.2, NS=16 (R=131072).  Scale 1: r=0.4, NS=32 (R=262144).
// ---------------------------------------------------------------------------

#define MTOT 8192
#define NPB  8192

__device__ float g_X0a[131072 * 128];
__device__ float g_X0b[262144 * 128];
__device__ int   g_idx0[8192 * 16];
__device__ int   g_idx1[8192 * 32];
__device__ float g_mx0[8192 * 128];
__device__ float g_mn0[8192 * 128];
__device__ float g_mx1[8192 * 128];
__device__ float g_mn1[8192 * 128];
__device__ float g_sumA[512];   // slots: 0=g1/s0, 1=g2/s0, 2=g1/s1, 3=g2/s1
__device__ float g_sqA[512];

__device__ __forceinline__ unsigned pack_h2(float lo, float hi) {
    __half2 h = __floats2half2_rn(lo, hi);
    return *(unsigned*)&h;
}

__device__ __forceinline__ void mma_f16(float* c, unsigned a0, unsigned a1,
                                        unsigned a2, unsigned a3, unsigned b0,
                                        unsigned b1) {
    asm volatile(
        "mma.sync.aligned.m16n8k16.row.col.f32.f16.f16.f32 "
        "{%0,%1,%2,%3}, {%4,%5,%6,%7}, {%8,%9}, {%0,%1,%2,%3};"
        : "+f"(c[0]), "+f"(c[1]), "+f"(c[2]), "+f"(c[3])
        : "r"(a0), "r"(a1), "r"(a2), "r"(a3), "r"(b0), "r"(b1));
}

// ---------------------------------------------------------------------------
// Merged ball query (exact fp32; folds stats zeroing + new_xyz copy).
// ---------------------------------------------------------------------------
__global__ void ballquery_merged(const float* __restrict__ xyz,
                                 const float* __restrict__ newxyz,
                                 float r2_0, float r2_1,
                                 const float* __restrict__ copySrc,
                                 float* __restrict__ copyDst, int copyN) {
    int tid = threadIdx.x;
    if (blockIdx.x == 0) {
        g_sumA[tid] = 0.0f; g_sumA[tid + 256] = 0.0f;
        g_sqA[tid]  = 0.0f; g_sqA[tid + 256]  = 0.0f;
    }
    int ct = blockIdx.x * 256 + tid;
    if (ct < copyN) copyDst[ct] = copySrc[ct];

    int gw   = (blockIdx.x * 256 + tid) >> 5;
    int lane = tid & 31;
    if (gw >= 2 * MTOT) return;
    int scl = gw >> 13;
    int q   = gw & (MTOT - 1);
    int NS  = scl ? 32 : 16;
    float r2 = scl ? r2_1 : r2_0;
    int* idx_out = (scl ? g_idx1 : g_idx0) + q * NS;

    int b = q >> 11;
    float qx = newxyz[q * 3 + 0];
    float qy = newxyz[q * 3 + 1];
    float qz = newxyz[q * 3 + 2];
    float qq = __fadd_rn(__fadd_rn(__fmul_rn(qx, qx), __fmul_rn(qy, qy)),
                         __fmul_rn(qz, qz));
    const float* P = xyz + (size_t)b * NPB * 3;
    int cnt = 0, first = -1;
    for (int start = 0; start < NPB; start += 32) {
        int i = start + lane;
        float px = P[i * 3 + 0];
        float py = P[i * 3 + 1];
        float pz = P[i * 3 + 2];
        float pp = __fadd_rn(__fadd_rn(__fmul_rn(px, px), __fmul_rn(py, py)),
                             __fmul_rn(pz, pz));
        float dt = __fadd_rn(__fadd_rn(__fmul_rn(qx, px), __fmul_rn(qy, py)),
                             __fmul_rn(qz, pz));
        float d2 = __fsub_rn(__fadd_rn(qq, pp), __fmul_rn(2.0f, dt));
        bool in = d2 < r2;
        unsigned mask = __ballot_sync(0xFFFFFFFFu, in);
        if (mask) {
            if (first < 0) first = start + (__ffs(mask) - 1);
            int pos = cnt + __popc(mask & ((1u << lane) - 1u));
            if (in && pos < NS) idx_out[pos] = i;
            cnt += __popc(mask);
            if (cnt >= NS) break;
        }
    }
    if (cnt == 0) {
        for (int j = lane; j < NS; j += 32) idx_out[j] = -1;
    } else if (cnt < NS) {
        for (int j = cnt + lane; j < NS; j += 32) idx_out[j] = first;
    }
}

// ---------------------------------------------------------------------------
// GEMM1 (fp16): X0[R,128] = gather(G)[R,80p] @ W0p^T. 512 thr, 16 warps
// (4m x 4n), warp 32x32, block 128x128, 2 row-tiles/block (W staged once).
// K-permuted (features 0..63, xyz 64..66, pad 79), f16x2 words, pitch 44.
// (unchanged from R16)
// ---------------------------------------------------------------------------
#define PH1 44
#define KH1 5
#define TILES1 2
#define SMEM1H ((128 * PH1 * 2 + 256) * 4)

__global__ __launch_bounds__(512, 2) void gemm1_merged(
    const float* __restrict__ xyz, const float* __restrict__ feat,
    const float* __restrict__ newxyz, const float* __restrict__ w00,
    const float* __restrict__ w10) {
    extern __shared__ unsigned sh[];
    unsigned* As = sh;              // [128][44] f16x2 words
    unsigned* Ws = sh + 128 * PH1;  // [128][44] f16x2 words
    float* s_sum = (float*)(sh + 2 * 128 * PH1);
    float* s_sq  = s_sum + 128;
    int tid = threadIdx.x;
    int bid = blockIdx.x;
    int scl = bid >= 512;
    int lb0 = (scl ? bid - 512 : bid) * TILES1;
    int nsShift = scl ? 5 : 4;
    const int* idx = scl ? g_idx1 : g_idx0;
    const float* w0 = scl ? w10 : w00;
    float* X0 = scl ? g_X0b : g_X0a;
    float* sum_out = g_sumA + (scl ? 256 : 0);
    float* sq_out  = g_sqA + (scl ? 256 : 0);

    if (tid < 128) { s_sum[tid] = 0.0f; s_sq[tid] = 0.0f; }
    for (int i = tid; i < 128 * 40; i += 512) {
        int o = i / 40, w = i - o * 40;
        const float* wr = w0 + o * 67;
        unsigned val;
        if (w < 32)
            val = pack_h2(wr[3 + 2 * w], wr[4 + 2 * w]);
        else if (w == 32)
            val = pack_h2(wr[0], wr[1]);
        else if (w == 33)
            val = pack_h2(wr[2], 0.0f);
        else
            val = 0u;
        Ws[o * PH1 + w] = val;
    }

    int lane = tid & 31, wid = tid >> 5;
    int wm = wid & 3, wn = wid >> 2;
    int gid = lane >> 2, t4 = lane & 3;
    const unsigned* Ab = As + (wm * 32 + gid) * PH1 + t4;
    const unsigned* Bb = Ws + (wn * 32 + gid) * PH1 + t4;

    for (int t = 0; t < TILES1; ++t) {
        if (t) __syncthreads();
        int row0 = (lb0 + t) * 128;
        {
            int r = tid >> 2, lw = tid & 3;
            int rg = row0 + r;
            int m  = rg >> nsShift;
            int p  = idx[rg];
            unsigned* grow = As + r * PH1;
            if (p < 0) {
#pragma unroll
                for (int w = lw * 10; w < lw * 10 + 10; ++w) grow[w] = 0u;
            } else {
                int gp = ((m >> 11) << 13) + p;
                const float4* frow = (const float4*)(feat + (size_t)gp * 64);
#pragma unroll
                for (int j = 0; j < 4; ++j) {
                    int f = lw + 4 * j;
                    float4 v = frow[f];
                    uint2 u;
                    u.x = pack_h2(v.x, v.y);
                    u.y = pack_h2(v.z, v.w);
                    *(uint2*)(grow + 2 * f) = u;
                }
                if (lw == 0) {
                    float dx = xyz[gp * 3 + 0] - newxyz[m * 3 + 0];
                    float dy = xyz[gp * 3 + 1] - newxyz[m * 3 + 1];
                    float dz = xyz[gp * 3 + 2] - newxyz[m * 3 + 2];
                    grow[32] = pack_h2(dx, dy);
                    grow[33] = pack_h2(dz, 0.0f);
                } else {
                    grow[32 + 2 * lw]     = 0u;
                    grow[32 + 2 * lw + 1] = 0u;
                }
            }
        }
        __syncthreads();

        float acc[2][4][4];
#pragma unroll
        for (int mt = 0; mt < 2; ++mt)
#pragma unroll
            for (int nt = 0; nt < 4; ++nt)
#pragma unroll
                for (int j = 0; j < 4; ++j) acc[mt][nt][j] = 0.0f;

#pragma unroll
        for (int ks = 0; ks < KH1; ++ks) {
            int k0 = ks * 8;
            unsigned a[2][4];
#pragma unroll
            for (int mt = 0; mt < 2; ++mt) {
                const unsigned* ap = Ab + mt * 16 * PH1 + k0;
                a[mt][0] = ap[0];
                a[mt][1] = ap[8 * PH1];
                a[mt][2] = ap[4];
                a[mt][3] = ap[8 * PH1 + 4];
            }
#pragma unroll
            for (int nt = 0; nt < 4; ++nt) {
                const unsigned* bp = Bb + nt * 8 * PH1 + k0;
                unsigned b0 = bp[0], b1 = bp[4];
                mma_f16(acc[0][nt], a[0][0], a[0][1], a[0][2], a[0][3], b0,
                        b1);
                mma_f16(acc[1][nt], a[1][0], a[1][1], a[1][2], a[1][3], b0,
                        b1);
            }
        }

#pragma unroll
        for (int mt = 0; mt < 2; ++mt) {
            int rbase = row0 + wm * 32 + mt * 16 + gid;
#pragma unroll
            for (int nt = 0; nt < 4; ++nt) {
                int cc = wn * 32 + nt * 8 + t4 * 2;
                *(float2*)(X0 + (size_t)rbase * 128 + cc) =
                    make_float2(acc[mt][nt][0], acc[mt][nt][1]);
                *(float2*)(X0 + (size_t)(rbase + 8) * 128 + cc) =
                    make_float2(acc[mt][nt][2], acc[mt][nt][3]);
            }
        }
#pragma unroll
        for (int nt = 0; nt < 4; ++nt) {
#pragma unroll
            for (int j = 0; j < 2; ++j) {
                float v0 = acc[0][nt][j], v1 = acc[0][nt][j + 2];
                float v2 = acc[1][nt][j], v3 = acc[1][nt][j + 2];
                float s = v0 + v1 + v2 + v3;
                float q = v0 * v0 + v1 * v1 + v2 * v2 + v3 * v3;
#pragma unroll
                for (int o = 4; o <= 16; o <<= 1) {
                    s += __shfl_xor_sync(0xFFFFFFFFu, s, o);
                    q += __shfl_xor_sync(0xFFFFFFFFu, q, o);
                }
                if (gid == 0) {
                    int c = wn * 32 + nt * 8 + t4 * 2 + j;
                    atomicAdd(&s_sum[c], s);
                    atomicAdd(&s_sq[c], q);
                }
            }
        }
    }
    __syncthreads();
    if (tid < 128) {
        atomicAdd(&sum_out[tid], s_sum[tid]);
        atomicAdd(&sq_out[tid], s_sq[tid]);
    }
}

// ---------------------------------------------------------------------------
// GEMM2 (per-scale, fp16, paired-word layout): 1024 threads, 32 warps
// (4m x 8n), warp 32x16, block 128x128, 2 row-tiles/block.
// Word w of each 8-word k16 group stored at slot 2*(w&3)+(w>>2): every mma
// fragment pair = one LDS.64. Pitch 72 (==8 mod 32) -> conflict-free.
// A register-prefetched; X1 stays in registers (max/min + stats fused).
// ---------------------------------------------------------------------------
#define PAH 72
#define KSH 8
#define TILES2 2
#define SMEM2H ((128 * PAH * 2 + 512) * 4)

template <int NS>
__global__ __launch_bounds__(1024) void gemm2_tc(
    const float* __restrict__ Xin, const float* __restrict__ w1,
    const float* __restrict__ gamma, const float* __restrict__ beta,
    float invR, const float* __restrict__ sum_in,
    const float* __restrict__ sq_in, float* __restrict__ sum_out,
    float* __restrict__ sq_out, float* __restrict__ mxp,
    float* __restrict__ mnp) {
    extern __shared__ unsigned sh[];
    unsigned* As = sh;               // [128][72] paired f16x2 words
    unsigned* Ws = sh + 128 * PAH;   // [128][72] paired f16x2 words
    float* s_sum = (float*)(sh + 2 * 128 * PAH);
    float* s_sq  = s_sum + 128;
    float* sc    = s_sq + 128;
    float* sf    = sc + 128;
    int tid = threadIdx.x;
    int lb0 = blockIdx.x * TILES2;

    float4 pf[4];
#pragma unroll
    for (int it = 0; it < 2; ++it) {
        int i = tid + it * 1024;
        int r = i >> 4, kg = i & 15;
        const float* src = Xin + (size_t)(lb0 * 128 + r) * 128 + kg * 8;
        pf[2 * it]     = *(const float4*)(src);
        pf[2 * it + 1] = *(const float4*)(src + 4);
    }

    if (tid < 128) {
        s_sum[tid] = 0.0f;
        s_sq[tid]  = 0.0f;
        float mean = sum_in[tid] * invR;
        float var  = sq_in[tid] * invR - mean * mean;
        float s    = gamma[tid] * rsqrtf(var + 1e-5f);
        sc[tid] = s;
        sf[tid] = fmaf(-mean, s, beta[tid]);
    }
    // stage W paired: thread covers 8 cols = 4 words of half a k16 group
    for (int i = tid; i < 128 * 16; i += 1024) {
        int o = i >> 4, kg = i & 15;
        int gg = kg >> 1, par = kg & 1;
        const float* wr = w1 + o * 128 + kg * 8;
        float4 v0 = *(const float4*)(wr);
        float4 v1 = *(const float4*)(wr + 4);
        unsigned* dst = Ws + o * PAH + gg * 8 + par;
        dst[0] = pack_h2(v0.x, v0.y);
        dst[2] = pack_h2(v0.z, v0.w);
        dst[4] = pack_h2(v1.x, v1.y);
        dst[6] = pack_h2(v1.z, v1.w);
    }
    __syncthreads();

    int lane = tid & 31, wid = tid >> 5;
    int wm = wid & 3, wn = wid >> 2;
    int gid = lane >> 2, t4 = lane & 3;
    const uint2* Ab = (const uint2*)(As + (wm * 32 + gid) * PAH) + t4;
    const uint2* Bb = (const uint2*)(Ws + (wn * 16 + gid) * PAH) + t4;

    for (int t = 0; t < TILES2; ++t) {
        // ---- BN + ReLU + f16 pack + paired STS from prefetch registers ----
#pragma unroll
        for (int it = 0; it < 2; ++it) {
            int i = tid + it * 1024;
            int r = i >> 4, kg = i & 15;
            int gg = kg >> 1, par = kg & 1;
            int kq = kg * 8;
            float4 v0 = pf[2 * it];
            float4 v1 = pf[2 * it + 1];
            float x0 = fmaxf(fmaf(sc[kq + 0], v0.x, sf[kq + 0]), 0.0f);
            float x1 = fmaxf(fmaf(sc[kq + 1], v0.y, sf[kq + 1]), 0.0f);
            float x2 = fmaxf(fmaf(sc[kq + 2], v0.z, sf[kq + 2]), 0.0f);
            float x3 = fmaxf(fmaf(sc[kq + 3], v0.w, sf[kq + 3]), 0.0f);
            float x4 = fmaxf(fmaf(sc[kq + 4], v1.x, sf[kq + 4]), 0.0f);
            float x5 = fmaxf(fmaf(sc[kq + 5], v1.y, sf[kq + 5]), 0.0f);
            float x6 = fmaxf(fmaf(sc[kq + 6], v1.z, sf[kq + 6]), 0.0f);
            float x7 = fmaxf(fmaf(sc[kq + 7], v1.w, sf[kq + 7]), 0.0f);
            unsigned* dst = As + r * PAH + gg * 8 + par;
            dst[0] = pack_h2(x0, x1);
            dst[2] = pack_h2(x2, x3);
            dst[4] = pack_h2(x4, x5);
            dst[6] = pack_h2(x6, x7);
        }
        __syncthreads();

        if (t + 1 < TILES2) {
#pragma unroll
            for (int it = 0; it < 2; ++it) {
                int i = tid + it * 1024;
                int r = i >> 4, kg = i & 15;
                const float* src =
                    Xin + (size_t)((lb0 + t + 1) * 128 + r) * 128 + kg * 8;
                pf[2 * it]     = *(const float4*)(src);
                pf[2 * it + 1] = *(const float4*)(src + 4);
            }
        }

        float acc[2][2][4];
#pragma unroll
        for (int mt = 0; mt < 2; ++mt)
#pragma unroll
            for (int nt = 0; nt < 2; ++nt)
#pragma unroll
                for (int j = 0; j < 4; ++j) acc[mt][nt][j] = 0.0f;

#pragma unroll
        for (int ks = 0; ks < KSH; ++ks) {
            // uint2 offsets: k16 group = 8 words = 4 uint2
            uint2 a02[2], a13[2];
#pragma unroll
            for (int mt = 0; mt < 2; ++mt) {
                a02[mt] = Ab[mt * (16 * PAH / 2) + ks * 4];
                a13[mt] = Ab[mt * (16 * PAH / 2) + (8 * PAH / 2) + ks * 4];
            }
#pragma unroll
            for (int nt = 0; nt < 2; ++nt) {
                uint2 b = Bb[nt * (8 * PAH / 2) + ks * 4];
                mma_f16(acc[0][nt], a02[0].x, a13[0].x, a02[0].y, a13[0].y,
                        b.x, b.y);
                mma_f16(acc[1][nt], a02[1].x, a13[1].x, a02[1].y, a13[1].y,
                        b.x, b.y);
            }
        }

        // ---- fused pooling + stats ----
#pragma unroll
        for (int nt = 0; nt < 2; ++nt) {
#pragma unroll
            for (int j = 0; j < 2; ++j) {
                int c = wn * 16 + nt * 8 + t4 * 2 + j;
                if (NS == 16) {
#pragma unroll
                    for (int mt = 0; mt < 2; ++mt) {
                        float mx = fmaxf(acc[mt][nt][j], acc[mt][nt][j + 2]);
                        float mn = fminf(acc[mt][nt][j], acc[mt][nt][j + 2]);
#pragma unroll
                        for (int o = 4; o <= 16; o <<= 1) {
                            mx = fmaxf(mx,
                                       __shfl_xor_sync(0xFFFFFFFFu, mx, o));
                            mn = fminf(mn,
                                       __shfl_xor_sync(0xFFFFFFFFu, mn, o));
                        }
                        if (gid == 0) {
                            int mq = (lb0 + t) * 8 + wm * 2 + mt;
                            mxp[mq * 128 + c] = mx;
                            mnp[mq * 128 + c] = mn;
                        }
                    }
                } else {
                    float mx = fmaxf(fmaxf(acc[0][nt][j], acc[0][nt][j + 2]),
                                     fmaxf(acc[1][nt][j], acc[1][nt][j + 2]));
                    float mn = fminf(fminf(acc[0][nt][j], acc[0][nt][j + 2]),
                                     fminf(acc[1][nt][j], acc[1][nt][j + 2]));
#pragma unroll
                    for (int o = 4; o <= 16; o <<= 1) {
                        mx = fmaxf(mx, __shfl_xor_sync(0xFFFFFFFFu, mx, o));
                        mn = fminf(mn, __shfl_xor_sync(0xFFFFFFFFu, mn, o));
                    }
                    if (gid == 0) {
                        int mq = (lb0 + t) * 4 + wm;
                        mxp[mq * 128 + c] = mx;
                        mnp[mq * 128 + c] = mn;
                    }
                }
                float v0 = acc[0][nt][j], v1 = acc[0][nt][j + 2];
                float v2 = acc[1][nt][j], v3 = acc[1][nt][j + 2];
                float s = v0 + v1 + v2 + v3;
                float q = v0 * v0 + v1 * v1 + v2 * v2 + v3 * v3;
#pragma unroll
                for (int o = 4; o <= 16; o <<= 1) {
                    s += __shfl_xor_sync(0xFFFFFFFFu, s, o);
                    q += __shfl_xor_sync(0xFFFFFFFFu, q, o);
                }
                if (gid == 0) {
                    atomicAdd(&s_sum[c], s);
                    atomicAdd(&s_sq[c], q);
                }
            }
        }
        if (t + 1 < TILES2) __syncthreads();
    }
    __syncthreads();
    if (tid < 128) {
        atomicAdd(&sum_out[tid], s_sum[tid]);
        atomicAdd(&sq_out[tid], s_sq[tid]);
    }
}

// ---------------------------------------------------------------------------
// Final: BN finalize inline on pooled raw values; pick max/min by sign(s).
// ---------------------------------------------------------------------------
__global__ void poolout(float* __restrict__ out, const float* __restrict__ g01,
                        const float* __restrict__ b01,
                        const float* __restrict__ g11,
                        const float* __restrict__ b11, float invR0,
                        float invR1) {
    int t = blockIdx.x * blockDim.x + threadIdx.x;
    int scl = t >= MTOT * 128;
    int tt = t - scl * MTOT * 128;
    int m = tt >> 7;
    int c = tt & 127;
    const float* sum_in = g_sumA + (scl ? 384 : 128);
    const float* sq_in  = g_sqA + (scl ? 384 : 128);
    const float* gamma = scl ? g11 : g01;
    const float* beta  = scl ? b11 : b01;
    float invR = scl ? invR1 : invR0;

    float mean = sum_in[c] * invR;
    float var  = sq_in[c] * invR - mean * mean;
    float s    = gamma[c] * rsqrtf(var + 1e-5f);
    float b    = fmaf(-mean, s, beta[c]);
    float mx = (scl ? g_mx1 : g_mx0)[tt];
    float mn = (scl ? g_mn1 : g_mn0)[tt];
    float v = (s >= 0.0f) ? mx : mn;
    out[(size_t)m * 256 + (scl ? 128 : 0) + c] = fmaxf(fmaf(s, v, b), 0.0f);
}

// ---------------------------------------------------------------------------
extern "C" void kernel_launch(void* const* d_in, const int* in_sizes, int n_in,
                              void* d_out, int out_size) {
    const float* xyz  = (const float*)d_in[0];
    const float* feat = (const float*)d_in[1];
    const float* nxyz = (const float*)d_in[2];
    const float* w00 = (const float*)d_in[5];
    const float* g00 = (const float*)d_in[6];
    const float* b00 = (const float*)d_in[7];
    const float* w01 = (const float*)d_in[8];
    const float* g01 = (const float*)d_in[9];
    const float* b01 = (const float*)d_in[10];
    const float* w10 = (const float*)d_in[11];
    const float* g10 = (const float*)d_in[12];
    const float* b10 = (const float*)d_in[13];
    const float* w11 = (const float*)d_in[14];
    const float* g11 = (const float*)d_in[15];
    const float* b11 = (const float*)d_in[16];

    float* outBase = (float*)d_out;
    int featOff = out_size - MTOT * 256;
    if (featOff < 0) featOff = 0;
    float* outF = outBase + featOff;

    cudaFuncSetAttribute(gemm1_merged,
                         cudaFuncAttributeMaxDynamicSharedMemorySize, SMEM1H);
    cudaFuncSetAttribute(gemm2_tc<16>,
                         cudaFuncAttributeMaxDynamicSharedMemorySize, SMEM2H);
    cudaFuncSetAttribute(gemm2_tc<32>,
                         cudaFuncAttributeMaxDynamicSharedMemorySize, SMEM2H);

    float* X0a;
    float* X0b;
    float* sumA;
    float* sqA;
    float* mx0;
    float* mn0;
    float* mx1;
    float* mn1;
    cudaGetSymbolAddress((void**)&X0a, g_X0a);
    cudaGetSymbolAddress((void**)&X0b, g_X0b);
    cudaGetSymbolAddress((void**)&sumA, g_sumA);
    cudaGetSymbolAddress((void**)&sqA, g_sqA);
    cudaGetSymbolAddress((void**)&mx0, g_mx0);
    cudaGetSymbolAddress((void**)&mn0, g_mn0);
    cudaGetSymbolAddress((void**)&mx1, g_mx1);
    cudaGetSymbolAddress((void**)&mn1, g_mn1);

    const float r2_0 = (float)(0.2 * 0.2);
    const float r2_1 = (float)(0.4 * 0.4);
    const float invR0 = 1.0f / 131072.0f;
    const float invR1 = 1.0f / 262144.0f;

    ballquery_merged<<<2048, 256>>>(xyz, nxyz, r2_0, r2_1, nxyz, outBase,
                                    featOff);
    gemm1_merged<<<1536, 512, SMEM1H>>>(xyz, feat, nxyz, w00, w10);
    // scale 1 first: gemm1's last-written X0b tail is still L2-resident
    gemm2_tc<32><<<1024, 1024, SMEM2H>>>(X0b, w11, g10, b10, invR1,
                                         sumA + 256, sqA + 256, sumA + 384,
                                         sqA + 384, mx1, mn1);
    gemm2_tc<16><<<512, 1024, SMEM2H>>>(X0a, w01, g00, b00, invR0, sumA + 0,
                                        sqA + 0, sumA + 128, sqA + 128, mx0,
                                        mn0);
    poolout<<<2 * MTOT * 128 / 256, 256>>>(outF, g01, b01, g11, b11, invR0,
                                           invR1);
}